// round 17
// baseline (speedup 1.0000x reference)
#include <cuda_runtime.h>
#include <cuda_bf16.h>
#include <math.h>
#include <stdint.h>

#define BB    4
#define TT    128
#define FRR   64
#define LL    8192
#define DIMM  384
#define NHEAD 12
#define HDIM  32
#define NTOK  (BB*LL)
#define QKVN  (3*DIMM)
#define FFN   (4*DIMM)

typedef __nv_bfloat16  bf16;
typedef __nv_bfloat162 bf162;

// ---------------------------------------------------------------------------
// Scratch
// ---------------------------------------------------------------------------
__device__ float g_xs  [(size_t)NTOK * DIMM];
__device__ bf16  g_xnb [(size_t)NTOK * DIMM];
__device__ bf16  g_qkvb[(size_t)NTOK * QKVN];
__device__ bf16  g_y1b [(size_t)NTOK * DIMM];
__device__ bf16  g_y2b [(size_t)NTOK * DIMM];
__device__ bf16  g_y3b [(size_t)NTOK * DIMM];
__device__ bf16  g_hb  [(size_t)NTOK * DIMM];
__device__ bf16  g_h1b [(size_t)NTOK * FFN];
__device__ bf16  g_wqkv [QKVN * DIMM];
__device__ bf16  g_wproj[DIMM * DIMM];
__device__ bf16  g_w1   [FFN * DIMM];
__device__ bf16  g_w2   [DIMM * FFN];

// ---------------------------------------------------------------------------
// common PTX helpers
// ---------------------------------------------------------------------------
__device__ __forceinline__ void cp16(uint32_t smem, const void* gmem) {
    asm volatile("cp.async.cg.shared.global [%0], [%1], 16;\n" :: "r"(smem), "l"(gmem));
}
#define CP_COMMIT() asm volatile("cp.async.commit_group;\n" ::: "memory")
#define CP_WAIT(n)  asm volatile("cp.async.wait_group %0;\n" :: "n"(n) : "memory")

__device__ __forceinline__ void ldsm4(unsigned& r0, unsigned& r1,
                                      unsigned& r2, unsigned& r3, unsigned addr) {
    asm volatile("ldmatrix.sync.aligned.m8n8.x4.shared.b16 {%0,%1,%2,%3}, [%4];\n"
                 : "=r"(r0), "=r"(r1), "=r"(r2), "=r"(r3) : "r"(addr));
}

__device__ __forceinline__ void mma_bf16(float* c, const unsigned* a, const unsigned* b) {
    asm volatile(
        "mma.sync.aligned.m16n8k16.row.col.f32.bf16.bf16.f32 "
        "{%0,%1,%2,%3}, {%4,%5,%6,%7}, {%8,%9}, {%0,%1,%2,%3};\n"
        : "+f"(c[0]), "+f"(c[1]), "+f"(c[2]), "+f"(c[3])
        : "r"(a[0]), "r"(a[1]), "r"(a[2]), "r"(a[3]), "r"(b[0]), "r"(b[1]));
}

__device__ __forceinline__ unsigned packbf(float lo, float hi) {
    bf162 v = __floats2bfloat162_rn(lo, hi);
    unsigned u;
    memcpy(&u, &v, 4);
    return u;
}

__device__ __forceinline__ float2 unpackbf(unsigned u) {
    bf162 v;
    memcpy(&v, &u, 4);
    return __bfloat1622float2(v);
}

__device__ __forceinline__ unsigned sum3w(unsigned a, unsigned b, unsigned c) {
    float2 fa = unpackbf(a), fb = unpackbf(b), fc = unpackbf(c);
    return packbf(fa.x + fb.x + fc.x, fa.y + fb.y + fc.y);
}

__device__ __forceinline__ float gelu_tanh(float x) {
    float c = 0.7978845608028654f;
    float t = tanhf(c * (x + 0.044715f * x * x * x));
    return 0.5f * x * (1.0f + t);
}

// ---------------------------------------------------------------------------
// Weight prep (all four weights in ONE launch):
// w [K][N] f32 -> wt [N][K] bf16, 32x32 tiles, flattened grid.
// ---------------------------------------------------------------------------
__device__ __forceinline__ void wprep_tile(const float* __restrict__ w,
                                           bf16* __restrict__ wt,
                                           int K, int N, int n0, int k0) {
    __shared__ float tile[32][33];
    int tx = threadIdx.x, ty = threadIdx.y;
    #pragma unroll
    for (int i = 0; i < 32; i += 8)
        tile[ty + i][tx] = w[(size_t)(k0 + ty + i) * N + n0 + tx];
    __syncthreads();
    #pragma unroll
    for (int i = 0; i < 32; i += 8)
        wt[(size_t)(n0 + ty + i) * K + k0 + tx] =
            __float2bfloat16_rn(tile[tx][ty + i]);
}

__global__ void wprep_all(const float* qkv_w, bf16* wq,
                          const float* proj_w, bf16* wp,
                          const float* w1, bf16* ww1,
                          const float* w2, bf16* ww2) {
    int r = blockIdx.x;
    if (r < 432) {                       // qkv: K=384, N=1152, nx=36
        int nx = r % 36, ny = r / 36;
        wprep_tile(qkv_w, wq, DIMM, QKVN, nx * 32, ny * 32);
    } else if (r < 576) {                // proj: K=384, N=384, nx=12
        int rr = r - 432;
        int nx = rr % 12, ny = rr / 12;
        wprep_tile(proj_w, wp, DIMM, DIMM, nx * 32, ny * 32);
    } else if (r < 1152) {               // w1: K=384, N=1536, nx=48
        int rr = r - 576;
        int nx = rr % 48, ny = rr / 48;
        wprep_tile(w1, ww1, DIMM, FFN, nx * 32, ny * 32);
    } else {                             // w2: K=1536, N=384, nx=12
        int rr = r - 1152;
        int nx = rr % 12, ny = rr / 12;
        wprep_tile(w2, ww2, FFN, DIMM, nx * 32, ny * 32);
    }
}

// ---------------------------------------------------------------------------
// Fused input transpose + rms1
// ---------------------------------------------------------------------------
__global__ __launch_bounds__(256)
void fuse_in_kernel(const float* __restrict__ x,
                    const float* __restrict__ n1,
                    float* __restrict__ xs, bf16* __restrict__ xnb) {
    __shared__ float tile[DIMM][17];
    __shared__ float rinv[16];
    int tid = threadIdx.x;
    int l0 = blockIdx.x * 16;
    int b  = blockIdx.y;
    const float* xb = x + (size_t)b * DIMM * LL + l0;

    #pragma unroll
    for (int it = 0; it < 24; it++) {
        int idx = tid + it * 256;
        int d = idx >> 4, c = idx & 15;
        tile[d][c] = xb[(size_t)d * LL + c];
    }
    __syncthreads();

    int tok = tid >> 4, j = tid & 15;
    float s = 0.f;
    #pragma unroll
    for (int k = 0; k < 24; k++) {
        float v = tile[j + 16 * k][tok];
        s += v * v;
    }
    #pragma unroll
    for (int m = 8; m >= 1; m >>= 1)
        s += __shfl_xor_sync(0xffffffffu, s, m);
    if (j == 0) rinv[tok] = rsqrtf(s * (1.0f / DIMM) + 1e-6f);
    __syncthreads();

    size_t gbase = ((size_t)b * LL + l0) * DIMM;
    #pragma unroll
    for (int it = 0; it < 24; it++) {
        int idx = tid + it * 256;
        int t2 = idx / DIMM, d = idx - t2 * DIMM;
        float raw = tile[d][t2];
        xs[gbase + (size_t)t2 * DIMM + d] = raw;
        xnb[gbase + (size_t)t2 * DIMM + d] =
            __float2bfloat16_rn(raw * rinv[t2] * n1[d]);
    }
}

// ---------------------------------------------------------------------------
// rms2
// ---------------------------------------------------------------------------
__global__ void rms_kernel(const float* __restrict__ in,
                           const float* __restrict__ scale,
                           bf16* __restrict__ out) {
    int tok = blockIdx.x;
    int tid = threadIdx.x;
    const float* row = in + (size_t)tok * DIMM;
    float v0 = row[tid], v1 = row[tid + 128], v2 = row[tid + 256];
    float s = v0*v0 + v1*v1 + v2*v2;
    #pragma unroll
    for (int off = 16; off > 0; off >>= 1)
        s += __shfl_down_sync(0xffffffffu, s, off);
    __shared__ float red[4];
    if ((tid & 31) == 0) red[tid >> 5] = s;
    __syncthreads();
    if (tid == 0) {
        float t = red[0] + red[1] + red[2] + red[3];
        red[0] = rsqrtf(t * (1.0f / DIMM) + 1e-6f);
    }
    __syncthreads();
    float rinv = red[0];
    bf16* orow = out + (size_t)tok * DIMM;
    orow[tid]       = __float2bfloat16_rn(v0 * rinv * scale[tid]);
    orow[tid + 128] = __float2bfloat16_rn(v1 * rinv * scale[tid + 128]);
    orow[tid + 256] = __float2bfloat16_rn(v2 * rinv * scale[tid + 256]);
}

// ---------------------------------------------------------------------------
// QK rms-norm + RoPE on bf16 qkv, warp-per-token. fp32 math inside.
// ---------------------------------------------------------------------------
__global__ __launch_bounds__(128)
void qkrope_kernel(bf16* __restrict__ qkv,
                   const float* __restrict__ nq,
                   const float* __restrict__ nk,
                   const float* __restrict__ cosT,
                   const float* __restrict__ sinT) {
    int tid = threadIdx.x;
    int lane = tid & 31;
    int tok = blockIdx.x * 4 + (tid >> 5);
    size_t base = (size_t)tok * QKVN;
    bf16* qp = qkv + base;
    bf16* kp = qkv + base + DIMM;

    float q[12], k[12];
    float ssq = 0.f, ssk = 0.f;
    #pragma unroll
    for (int i = 0; i < 3; i++) {
        int e0 = i * 128 + lane * 4;
        uint2 qw = *(const uint2*)(qp + e0);
        uint2 kw = *(const uint2*)(kp + e0);
        float2 qa = unpackbf(qw.x), qb = unpackbf(qw.y);
        float2 ka = unpackbf(kw.x), kb = unpackbf(kw.y);
        q[i*4+0] = qa.x; q[i*4+1] = qa.y; q[i*4+2] = qb.x; q[i*4+3] = qb.y;
        k[i*4+0] = ka.x; k[i*4+1] = ka.y; k[i*4+2] = kb.x; k[i*4+3] = kb.y;
        ssq += qa.x*qa.x + qa.y*qa.y + qb.x*qb.x + qb.y*qb.y;
        ssk += ka.x*ka.x + ka.y*ka.y + kb.x*kb.x + kb.y*kb.y;
    }
    #pragma unroll
    for (int m = 16; m >= 1; m >>= 1) {
        ssq += __shfl_xor_sync(0xffffffffu, ssq, m);
        ssk += __shfl_xor_sync(0xffffffffu, ssk, m);
    }
    float rq = rsqrtf(ssq * (1.0f / DIMM) + 1e-6f);
    float rk = rsqrtf(ssk * (1.0f / DIMM) + 1e-6f);

    int l = tok & (LL - 1);
    int j2 = 2 * (lane & 7);
    float c0 = cosT[l * 16 + j2],     s0 = sinT[l * 16 + j2];
    float c1 = cosT[l * 16 + j2 + 1], s1 = sinT[l * 16 + j2 + 1];

    #pragma unroll
    for (int i = 0; i < 3; i++) {
        int e0 = i * 128 + lane * 4;
        float4 nqv = *(const float4*)(nq + e0);
        float4 nkv = *(const float4*)(nk + e0);
        float a0 = q[i*4+0] * rq * nqv.x, a1 = q[i*4+1] * rq * nqv.y;
        float a2 = q[i*4+2] * rq * nqv.z, a3 = q[i*4+3] * rq * nqv.w;
        uint2 qo;
        qo.x = packbf(a0 * c0 - a1 * s0, a0 * s0 + a1 * c0);
        qo.y = packbf(a2 * c1 - a3 * s1, a2 * s1 + a3 * c1);
        *(uint2*)(qp + e0) = qo;
        float b0 = k[i*4+0] * rk * nkv.x, b1 = k[i*4+1] * rk * nkv.y;
        float b2 = k[i*4+2] * rk * nkv.z, b3 = k[i*4+3] * rk * nkv.w;
        uint2 ko;
        ko.x = packbf(b0 * c0 - b1 * s0, b0 * s0 + b1 * c0);
        ko.y = packbf(b2 * c1 - b3 * s1, b2 * s1 + b3 * c1);
        *(uint2*)(kp + e0) = ko;
    }
}

// ---------------------------------------------------------------------------
// Tensor-core attention (unchanged from R16)
// ---------------------------------------------------------------------------
template <int VAR>
__device__ __forceinline__ int tok_of(int g, int s) {
    if (VAR == 0) { int b = g >> 7, t = g & 127; return b * LL + t * FRR + s; }
    if (VAR == 1) { int b = g >> 6, fr = g & 63; return b * LL + s * FRR + fr; }
    int b = g >> 8, r = g & 255;
    int t1 = r >> 3, f1 = r & 7;
    int t2 = s >> 3, f2 = s & 7;
    return b * LL + (t1 * 4 + t2) * FRR + f1 * 8 + f2;
}

template <int VAR, int S>
__global__ __launch_bounds__(128)
void attn_mma(const bf16* __restrict__ qkv, bf16* __restrict__ yout) {
    extern __shared__ char asmem[];
    constexpr int QSTR = 40;
    constexpr int VSTR = S + 8;
    constexpr int QSZ  = S * QSTR;
    constexpr int VTSZ = 32 * VSTR;
    constexpr int JOB  = 2 * QSZ + VTSZ;

    int tid = threadIdx.x, wid = tid >> 5, lane = tid & 31;
    int g = blockIdx.x * 4 + wid;
    int h = blockIdx.y;

    bf16* Qs = (bf16*)asmem + (size_t)wid * JOB;
    bf16* Ks = Qs + QSZ;
    bf16* Vt = Ks + QSZ;

    for (int j = 0; j < S; j++) {
        size_t base = (size_t)tok_of<VAR>(g, j) * QKVN + h * HDIM + lane;
        bf16 qv = qkv[base];
        bf16 kv = qkv[base + 384];
        bf16 vv = qkv[base + 768];
        Qs[j * QSTR + lane] = qv;
        Ks[j * QSTR + lane] = kv;
        Vt[lane * VSTR + j] = vv;
    }
    __syncwarp();

    uint32_t Qu = (uint32_t)__cvta_generic_to_shared(Qs);
    uint32_t Ku = (uint32_t)__cvta_generic_to_shared(Ks);
    uint32_t Vu = (uint32_t)__cvta_generic_to_shared(Vt);

    int mrow = lane & 7, sel = lane >> 3;
    int a_row = (sel & 1) * 8 + mrow, a_k = (sel >> 1) * 8;
    int b_row = (sel >> 1) * 8 + mrow, b_k = (sel & 1) * 8;
    int gid = lane >> 2, tid4 = lane & 3;
    const float rscale = 0.17677669529663687f;

    for (int mt = 0; mt < S / 16; mt++) {
        unsigned aq[2][4];
        #pragma unroll
        for (int ks = 0; ks < 2; ks++) {
            uint32_t addr = Qu +
                (uint32_t)((mt * 16 + a_row) * QSTR + ks * 16 + a_k) * 2;
            ldsm4(aq[ks][0], aq[ks][1], aq[ks][2], aq[ks][3], addr);
        }

        float cy[4][4];
        #pragma unroll
        for (int nt = 0; nt < 4; nt++)
            #pragma unroll
            for (int r = 0; r < 4; r++) cy[nt][r] = 0.f;
        float ls0 = 0.f, ls1 = 0.f;

        for (int jt = 0; jt < S / 16; jt++) {
            unsigned bk[2][2][2];
            #pragma unroll
            for (int ks = 0; ks < 2; ks++) {
                uint32_t addr = Ku +
                    (uint32_t)((jt * 16 + b_row) * QSTR + ks * 16 + b_k) * 2;
                ldsm4(bk[ks][0][0], bk[ks][0][1], bk[ks][1][0], bk[ks][1][1], addr);
            }
            float sc[2][4];
            #pragma unroll
            for (int nt = 0; nt < 2; nt++)
                #pragma unroll
                for (int r = 0; r < 4; r++) sc[nt][r] = 0.f;
            #pragma unroll
            for (int ks = 0; ks < 2; ks++)
                #pragma unroll
                for (int nt = 0; nt < 2; nt++)
                    mma_bf16(sc[nt], aq[ks], bk[ks][nt]);

            float p00 = __expf(sc[0][0] * rscale), p01 = __expf(sc[0][1] * rscale);
            float p02 = __expf(sc[0][2] * rscale), p03 = __expf(sc[0][3] * rscale);
            float p10 = __expf(sc[1][0] * rscale), p11 = __expf(sc[1][1] * rscale);
            float p12 = __expf(sc[1][2] * rscale), p13 = __expf(sc[1][3] * rscale);
            ls0 += p00 + p01 + p10 + p11;
            ls1 += p02 + p03 + p12 + p13;
            unsigned pa[4];
            pa[0] = packbf(p00, p01);
            pa[1] = packbf(p02, p03);
            pa[2] = packbf(p10, p11);
            pa[3] = packbf(p12, p13);

            unsigned bv[4][2];
            #pragma unroll
            for (int np = 0; np < 2; np++) {
                uint32_t addr = Vu +
                    (uint32_t)((np * 16 + b_row) * VSTR + jt * 16 + b_k) * 2;
                ldsm4(bv[2*np][0], bv[2*np][1], bv[2*np+1][0], bv[2*np+1][1], addr);
            }
            #pragma unroll
            for (int nt = 0; nt < 4; nt++)
                mma_bf16(cy[nt], pa, bv[nt]);
        }

        ls0 += __shfl_xor_sync(0xffffffffu, ls0, 1);
        ls0 += __shfl_xor_sync(0xffffffffu, ls0, 2);
        ls1 += __shfl_xor_sync(0xffffffffu, ls1, 1);
        ls1 += __shfl_xor_sync(0xffffffffu, ls1, 2);
        float inv0 = 1.f / ls0, inv1 = 1.f / ls1;

        int r0 = mt * 16 + gid, r1 = r0 + 8;
        size_t o0 = (size_t)tok_of<VAR>(g, r0) * DIMM + h * HDIM;
        size_t o1 = (size_t)tok_of<VAR>(g, r1) * DIMM + h * HDIM;
        #pragma unroll
        for (int nt = 0; nt < 4; nt++) {
            int cc = nt * 8 + 2 * tid4;
            *(bf162*)(yout + o0 + cc) =
                __floats2bfloat162_rn(cy[nt][0] * inv0, cy[nt][1] * inv0);
            *(bf162*)(yout + o1 + cc) =
                __floats2bfloat162_rn(cy[nt][2] * inv1, cy[nt][3] * inv1);
        }
    }
}

#define ATTN_SMEM(S) (4 * (2 * (S) * 40 + 32 * ((S) + 8)) * 2)

// ---------------------------------------------------------------------------
// bf16 mma.sync GEMM (2-stage cp.async, ldmatrix, GBK=64)
// EPI 1: bf16 gelu store; 2: f32 +=; 3: bf16 store;
// EPI 4: Res + result, transposed f32 store to out (B,DIM,L).
// SUMA: A tile = bf16(f32(A) + f32(A2) + f32(A3)) computed in the loader.
// ---------------------------------------------------------------------------
#define GBM 128
#define GBN 128
#define GBK 64
#define KSTR 72
#define ATILE (2 * GBM * KSTR)
#define GEMM_SMEM_BYTES (2 * ATILE * 2)
#define TSTR 129

template <int EPI, bool SUMA>
__global__ __launch_bounds__(256)
void mma_gemm(const bf16* __restrict__ A, const bf16* __restrict__ A2,
              const bf16* __restrict__ A3, const bf16* __restrict__ Wt,
              const float* __restrict__ bias, void* __restrict__ Cv,
              const float* __restrict__ Res,
              int M, int N, int K) {
    extern __shared__ char dynsmem[];
    bf16* As = (bf16*)dynsmem;
    bf16* Bs = (bf16*)(dynsmem + ATILE * 2);

    int tid  = threadIdx.x;
    int n0   = blockIdx.x * GBN, m0 = blockIdx.y * GBM;
    int warp = tid >> 5, lane = tid & 31;
    int wm   = (warp & 3) * 32;
    int wn   = (warp >> 2) * 64;

    size_t aoff = (size_t)m0 * K;
    const bf16* Abase  = A + aoff;
    const bf16* A2base = SUMA ? A2 + aoff : nullptr;
    const bf16* A3base = SUMA ? A3 + aoff : nullptr;
    const bf16* Bbase  = Wt + (size_t)n0 * K;

    int mrow = lane & 7;
    int sel  = lane >> 3;
    int a_row_add = (sel & 1) * 8 + mrow;
    int a_k_add   = (sel >> 1) * 8;
    int b_row_add = (sel >> 1) * 8 + mrow;
    int b_k_add   = (sel & 1) * 8;

    uint32_t As_u = (uint32_t)__cvta_generic_to_shared(As);
    uint32_t Bs_u = (uint32_t)__cvta_generic_to_shared(Bs);

    float c[2][8][4];
    #pragma unroll
    for (int mt = 0; mt < 2; mt++)
        #pragma unroll
        for (int nt = 0; nt < 8; nt++)
            #pragma unroll
            for (int r = 0; r < 4; r++) c[mt][nt][r] = 0.f;

    auto load_tiles = [&](int buf, int k0) {
        bf16* Ad = As + buf * GBM * KSTR;
        bf16* Bd = Bs + buf * GBN * KSTR;
        #pragma unroll
        for (int i = 0; i < 4; i++) {
            int ch = tid + i * 256;
            int r = ch >> 3, cc = ch & 7;
            size_t go = (size_t)r * K + k0 + cc * 8;
            if (SUMA) {
                uint4 a = *(const uint4*)(Abase  + go);
                uint4 b = *(const uint4*)(A2base + go);
                uint4 d = *(const uint4*)(A3base + go);
                uint4 rr;
                rr.x = sum3w(a.x, b.x, d.x);
                rr.y = sum3w(a.y, b.y, d.y);
                rr.z = sum3w(a.z, b.z, d.z);
                rr.w = sum3w(a.w, b.w, d.w);
                *(uint4*)(Ad + r * KSTR + cc * 8) = rr;
            } else {
                cp16((uint32_t)__cvta_generic_to_shared(Ad + r * KSTR + cc * 8),
                     Abase + go);
            }
            cp16((uint32_t)__cvta_generic_to_shared(Bd + r * KSTR + cc * 8),
                 Bbase + go);
        }
    };

    int kTiles = K / GBK;
    load_tiles(0, 0);
    CP_COMMIT();

    for (int kt = 0; kt < kTiles; kt++) {
        int buf = kt & 1;
        if (kt + 1 < kTiles) {
            load_tiles(buf ^ 1, (kt + 1) * GBK);
            CP_COMMIT();
            CP_WAIT(1);
        } else {
            CP_WAIT(0);
        }
        __syncthreads();

        uint32_t Abuf = As_u + (uint32_t)(buf * GBM * KSTR) * 2;
        uint32_t Bbuf = Bs_u + (uint32_t)(buf * GBN * KSTR) * 2;

        #pragma unroll
        for (int ks = 0; ks < GBK; ks += 16) {
            unsigned af[2][4], bfr[8][2];
            #pragma unroll
            for (int mt = 0; mt < 2; mt++) {
                uint32_t addr = Abuf +
                    (uint32_t)((wm + mt * 16 + a_row_add) * KSTR + ks + a_k_add) * 2;
                ldsm4(af[mt][0], af[mt][1], af[mt][2], af[mt][3], addr);
            }
            #pragma unroll
            for (int np = 0; np < 4; np++) {
                uint32_t addr = Bbuf +
                    (uint32_t)((wn + np * 16 + b_row_add) * KSTR + ks + b_k_add) * 2;
                ldsm4(bfr[2*np][0], bfr[2*np][1], bfr[2*np+1][0], bfr[2*np+1][1], addr);
            }
            #pragma unroll
            for (int mt = 0; mt < 2; mt++)
                #pragma unroll
                for (int nt = 0; nt < 8; nt++)
                    mma_bf16(c[mt][nt], af[mt], bfr[nt]);
        }
        __syncthreads();
    }

    int gid  = lane >> 2, tid4 = lane & 3;

    if (EPI == 4) {
        float* tileT = (float*)dynsmem;
        #pragma unroll
        for (int mt = 0; mt < 2; mt++) {
            int lr0 = wm + mt * 16 + gid;
            int lr1 = lr0 + 8;
            #pragma unroll
            for (int nt = 0; nt < 8; nt++) {
                int lc = wn + nt * 8 + 2 * tid4;
                float b0 = bias[n0 + lc], b1 = bias[n0 + lc + 1];
                const float* r0p = Res + (size_t)(m0 + lr0) * N + n0 + lc;
                const float* r1p = Res + (size_t)(m0 + lr1) * N + n0 + lc;
                float2 o0 = *(const float2*)r0p, o1 = *(const float2*)r1p;
                tileT[lr0 * TSTR + lc]     = o0.x + c[mt][nt][0] + b0;
                tileT[lr0 * TSTR + lc + 1] = o0.y + c[mt][nt][1] + b1;
                tileT[lr1 * TSTR + lc]     = o1.x + c[mt][nt][2] + b0;
                tileT[lr1 * TSTR + lc + 1] = o1.y + c[mt][nt][3] + b1;
            }
        }
        __syncthreads();
        float* outp = (float*)Cv;
        int bb = m0 >> 13;
        int l0 = m0 & (LL - 1);
        int dcol = tid >> 1;
        int half = (tid & 1) * 64;
        float* orow = outp + (size_t)bb * DIMM * LL + (size_t)(n0 + dcol) * LL + l0 + half;
        #pragma unroll
        for (int t = 0; t < 64; t += 4) {
            float4 v;
            v.x = tileT[(half + t + 0) * TSTR + dcol];
            v.y = tileT[(half + t + 1) * TSTR + dcol];
            v.z = tileT[(half + t + 2) * TSTR + dcol];
            v.w = tileT[(half + t + 3) * TSTR + dcol];
            *(float4*)(orow + t) = v;
        }
        return;
    }

    #pragma unroll
    for (int mt = 0; mt < 2; mt++) {
        int r0 = m0 + wm + mt * 16 + gid;
        int r1 = r0 + 8;
        #pragma unroll
        for (int nt = 0; nt < 8; nt++) {
            int cc = n0 + wn + nt * 8 + 2 * tid4;
            float b0 = bias[cc], b1 = bias[cc + 1];
            float v00 = c[mt][nt][0] + b0, v01 = c[mt][nt][1] + b1;
            float v10 = c[mt][nt][2] + b0, v11 = c[mt][nt][3] + b1;
            if (EPI == 1) {
                bf16* C = (bf16*)Cv;
                *(bf162*)(C + (size_t)r0 * N + cc) =
                    __floats2bfloat162_rn(gelu_tanh(v00), gelu_tanh(v01));
                *(bf162*)(C + (size_t)r1 * N + cc) =
                    __floats2bfloat162_rn(gelu_tanh(v10), gelu_tanh(v11));
            } else if (EPI == 2) {
                float* C = (float*)Cv;
                float* p0 = C + (size_t)r0 * N + cc;
                float* p1 = C + (size_t)r1 * N + cc;
                float2 o0 = *(float2*)p0, o1 = *(float2*)p1;
                *(float2*)p0 = make_float2(o0.x + v00, o0.y + v01);
                *(float2*)p1 = make_float2(o1.x + v10, o1.y + v11);
            } else {
                bf16* C = (bf16*)Cv;
                *(bf162*)(C + (size_t)r0 * N + cc) = __floats2bfloat162_rn(v00, v01);
                *(bf162*)(C + (size_t)r1 * N + cc) = __floats2bfloat162_rn(v10, v11);
            }
        }
    }
}

// ---------------------------------------------------------------------------
// kernel_launch
// ---------------------------------------------------------------------------
extern "C" void kernel_launch(void* const* d_in, const int* in_sizes, int n_in,
                              void* d_out, int out_size) {
    const float* x      = (const float*)d_in[0];
    const float* cosT   = (const float*)d_in[1];
    const float* sinT   = (const float*)d_in[2];
    const float* qkv_w  = (const float*)d_in[3];
    const float* qkv_b  = (const float*)d_in[4];
    const float* nq_s   = (const float*)d_in[5];
    const float* nk_s   = (const float*)d_in[6];
    const float* proj_w = (const float*)d_in[7];
    const float* proj_b = (const float*)d_in[8];
    const float* n1_s   = (const float*)d_in[9];
    const float* n2_s   = (const float*)d_in[10];
    const float* w1     = (const float*)d_in[11];
    const float* b1     = (const float*)d_in[12];
    const float* w2     = (const float*)d_in[13];
    const float* b2     = (const float*)d_in[14];
    float* out = (float*)d_out;

    float *xs;
    bf16 *xnb, *qkvb, *y1b, *y2b, *y3b, *hb, *h1b, *wq, *wp, *ww1, *ww2;
    cudaGetSymbolAddress((void**)&xs,   g_xs);
    cudaGetSymbolAddress((void**)&xnb,  g_xnb);
    cudaGetSymbolAddress((void**)&qkvb, g_qkvb);
    cudaGetSymbolAddress((void**)&y1b,  g_y1b);
    cudaGetSymbolAddress((void**)&y2b,  g_y2b);
    cudaGetSymbolAddress((void**)&y3b,  g_y3b);
    cudaGetSymbolAddress((void**)&hb,   g_hb);
    cudaGetSymbolAddress((void**)&h1b,  g_h1b);
    cudaGetSymbolAddress((void**)&wq,   g_wqkv);
    cudaGetSymbolAddress((void**)&wp,   g_wproj);
    cudaGetSymbolAddress((void**)&ww1,  g_w1);
    cudaGetSymbolAddress((void**)&ww2,  g_w2);

    cudaFuncSetAttribute((const void*)mma_gemm<1,false>, cudaFuncAttributeMaxDynamicSharedMemorySize, GEMM_SMEM_BYTES);
    cudaFuncSetAttribute((const void*)mma_gemm<2,true>,  cudaFuncAttributeMaxDynamicSharedMemorySize, GEMM_SMEM_BYTES);
    cudaFuncSetAttribute((const void*)mma_gemm<3,false>, cudaFuncAttributeMaxDynamicSharedMemorySize, GEMM_SMEM_BYTES);
    cudaFuncSetAttribute((const void*)mma_gemm<4,false>, cudaFuncAttributeMaxDynamicSharedMemorySize, GEMM_SMEM_BYTES);
    cudaFuncSetAttribute((const void*)attn_mma<0, 64>,  cudaFuncAttributeMaxDynamicSharedMemorySize, ATTN_SMEM(64));
    cudaFuncSetAttribute((const void*)attn_mma<1, 128>, cudaFuncAttributeMaxDynamicSharedMemorySize, ATTN_SMEM(128));
    cudaFuncSetAttribute((const void*)attn_mma<2, 32>,  cudaFuncAttributeMaxDynamicSharedMemorySize, ATTN_SMEM(32));

    // all four weight preps in one launch
    wprep_all<<<1728, dim3(32, 8)>>>(qkv_w, wq, proj_w, wp, w1, ww1, w2, ww2);

    // fused transpose + rms1
    fuse_in_kernel<<<dim3(LL/16, BB), 256>>>(x, n1_s, xs, xnb);

    // qkvb = bf16(xnb @ wq^T + qkv_b)
    mma_gemm<3,false><<<dim3(QKVN/GBN, NTOK/GBM), 256, GEMM_SMEM_BYTES>>>(
        xnb, nullptr, nullptr, wq, qkv_b, qkvb, nullptr, NTOK, QKVN, DIMM);

    // q/k rmsnorm + rope
    qkrope_kernel<<<NTOK/4, 128>>>(qkvb, nq_s, nk_s, cosT, sinT);

    // three attentions -> independent bf16 buffers
    attn_mma<0, 64 ><<<dim3(BB * TT / 4,  NHEAD), 128, ATTN_SMEM(64)>>>(qkvb, y1b);
    attn_mma<1, 128><<<dim3(BB * FRR / 4, NHEAD), 128, ATTN_SMEM(128)>>>(qkvb, y2b);
    attn_mma<2, 32 ><<<dim3(BB * 256 / 4, NHEAD), 128, ATTN_SMEM(32)>>>(qkvb, y3b);

    // xs += (y1+y2+y3) @ wp^T + proj_b   (sum3 fused into A loader)
    mma_gemm<2,true><<<dim3(DIMM/GBN, NTOK/GBM), 256, GEMM_SMEM_BYTES>>>(
        y1b, y2b, y3b, wp, proj_b, xs, nullptr, NTOK, DIMM, DIMM);

    // hb = bf16(rms(xs, n2))
    rms_kernel<<<NTOK, 128>>>(xs, n2_s, hb);

    // h1b = bf16(gelu(hb @ ww1^T + b1))
    mma_gemm<1,false><<<dim3(FFN/GBN, NTOK/GBM), 256, GEMM_SMEM_BYTES>>>(
        hb, nullptr, nullptr, ww1, b1, h1b, nullptr, NTOK, FFN, DIMM);

    // out = transpose(xs + h1b @ ww2^T + b2)
    mma_gemm<4,false><<<dim3(DIMM/GBN, NTOK/GBM), 256, GEMM_SMEM_BYTES>>>(
        h1b, nullptr, nullptr, ww2, b2, out, xs, NTOK, DIMM, FFN);
}